// round 16
// baseline (speedup 1.0000x reference)
#include <cuda_runtime.h>
#include <cuda_bf16.h>
#include <cuda_fp16.h>
#include <math.h>
#include <stdint.h>

#define BB 256
#define SS 8192
#define FF 2048
#define KNB 20

// ---------------- scratch ----------------
static __device__ float g_x [BB * FF];    // normalized inputs0
static __device__ float g_Z [2 * BB];     // row sumexp (softmax0, softmax1)
static __device__ float g_lZ[2 * BB];     // m + log Z
static __device__ float g_Zn[BB];         // NCE row sum of exp(score - 20)
static __device__ float g_acc[4];         // nce, SCE(=Σ ln1·lp0), Σ lp0t, Σ kl

// bf16 images for the big GEMM
static __device__ __align__(16) __nv_bfloat16 g_Ah[BB * FF];
static __device__ __align__(16) __nv_bfloat16 g_Bh[SS * FF];

// fp16 softmax-numerator image for the neighbor GEMM (rows = contraction index k)
static __device__ __align__(16) __half g_Eh [2 * BB * SS];  // [512][8192]
static __device__ __align__(16) __half g_Wh [2 * BB * 2 * BB]; // [512][512], x1024

// ---------------- helpers ----------------
__device__ __forceinline__ uint32_t smem_u32(const void* p) {
    uint32_t a;
    asm("{ .reg .u64 t; cvta.to.shared.u64 t, %1; cvt.u32.u64 %0, t; }" : "=r"(a) : "l"(p));
    return a;
}
__device__ __forceinline__ void cp16(uint32_t d, const void* s) {
    asm volatile("cp.async.cg.shared.global [%0], [%1], 16;" :: "r"(d), "l"(s));
}
__device__ __forceinline__ void cp_commit() {
    asm volatile("cp.async.commit_group;" ::: "memory");
}
__device__ __forceinline__ void cp_wait2() {
    asm volatile("cp.async.wait_group 2;" ::: "memory");
}
__device__ __forceinline__ void cp_wait4() {
    asm volatile("cp.async.wait_group 4;" ::: "memory");
}
__device__ __forceinline__ void ldsm4(uint32_t* r, uint32_t a) {
    asm volatile("ldmatrix.sync.aligned.m8n8.x4.shared.b16 {%0,%1,%2,%3}, [%4];"
                 : "=r"(r[0]), "=r"(r[1]), "=r"(r[2]), "=r"(r[3]) : "r"(a));
}
__device__ __forceinline__ void ldsm4t(uint32_t* r, uint32_t a) {
    asm volatile("ldmatrix.sync.aligned.m8n8.x4.trans.shared.b16 {%0,%1,%2,%3}, [%4];"
                 : "=r"(r[0]), "=r"(r[1]), "=r"(r[2]), "=r"(r[3]) : "r"(a));
}
__device__ __forceinline__ void mma_bf16(float* c, const uint32_t* a, uint32_t b0, uint32_t b1) {
    asm volatile("mma.sync.aligned.m16n8k16.row.col.f32.bf16.bf16.f32 "
                 "{%0,%1,%2,%3},{%4,%5,%6,%7},{%8,%9},{%0,%1,%2,%3};"
                 : "+f"(c[0]), "+f"(c[1]), "+f"(c[2]), "+f"(c[3])
                 : "r"(a[0]), "r"(a[1]), "r"(a[2]), "r"(a[3]), "r"(b0), "r"(b1));
}
__device__ __forceinline__ void mma_f16(float* c, const uint32_t* a, uint32_t b0, uint32_t b1) {
    asm volatile("mma.sync.aligned.m16n8k16.row.col.f32.f16.f16.f32 "
                 "{%0,%1,%2,%3},{%4,%5,%6,%7},{%8,%9},{%0,%1,%2,%3};"
                 : "+f"(c[0]), "+f"(c[1]), "+f"(c[2]), "+f"(c[3])
                 : "r"(a[0]), "r"(a[1]), "r"(a[2]), "r"(a[3]), "r"(b0), "r"(b1));
}

// ---------------- reductions ----------------
__device__ __forceinline__ float bsum(float v) {
    __shared__ float sh[33];
    int lane = threadIdx.x & 31, w = threadIdx.x >> 5, nw = (blockDim.x + 31) >> 5;
    #pragma unroll
    for (int o = 16; o; o >>= 1) v += __shfl_xor_sync(0xffffffffu, v, o);
    if (lane == 0) sh[w] = v;
    __syncthreads();
    v = (threadIdx.x < nw) ? sh[threadIdx.x] : 0.f;
    if (w == 0) {
        #pragma unroll
        for (int o = 16; o; o >>= 1) v += __shfl_xor_sync(0xffffffffu, v, o);
        if (lane == 0) sh[32] = v;
    }
    __syncthreads();
    v = sh[32];
    __syncthreads();
    return v;
}
__device__ __forceinline__ float bmax(float v) {
    __shared__ float sh[33];
    int lane = threadIdx.x & 31, w = threadIdx.x >> 5, nw = (blockDim.x + 31) >> 5;
    #pragma unroll
    for (int o = 16; o; o >>= 1) v = fmaxf(v, __shfl_xor_sync(0xffffffffu, v, o));
    if (lane == 0) sh[w] = v;
    __syncthreads();
    v = (threadIdx.x < nw) ? sh[threadIdx.x] : -1e30f;
    if (w == 0) {
        #pragma unroll
        for (int o = 16; o; o >>= 1) v = fmaxf(v, __shfl_xor_sync(0xffffffffu, v, o));
        if (lane == 0) sh[32] = v;
    }
    __syncthreads();
    v = sh[32];
    __syncthreads();
    return v;
}

// ---------------- kernels ----------------
// normalize inputs0 -> g_x + bf16 rows; block 0 zeroes chain1 accumulators. grid=BB
__global__ void k_norm(const float* __restrict__ in) {
    int b = blockIdx.x, t = threadIdx.x;
    if (b == 0) {
        g_Zn[t] = 0.f;
        if (t == 0) g_acc[0] = 0.f;
    }
    const float4* r = (const float4*)(in + (size_t)b * FF);
    float4 v0 = r[2 * t], v1 = r[2 * t + 1];
    float s = v0.x*v0.x + v0.y*v0.y + v0.z*v0.z + v0.w*v0.w
            + v1.x*v1.x + v1.y*v1.y + v1.z*v1.z + v1.w*v1.w;
    s = bsum(s);
    float inv = 1.f / fmaxf(sqrtf(s), 1e-12f);
    v0.x *= inv; v0.y *= inv; v0.z *= inv; v0.w *= inv;
    v1.x *= inv; v1.y *= inv; v1.z *= inv; v1.w *= inv;
    float4* o = (float4*)(g_x + (size_t)b * FF);
    o[2 * t] = v0; o[2 * t + 1] = v1;
    float v[8] = { v0.x, v0.y, v0.z, v0.w, v1.x, v1.y, v1.z, v1.w };
    __align__(16) unsigned short h[8];
    #pragma unroll
    for (int i = 0; i < 8; i++) h[i] = __bfloat16_as_ushort(__float2bfloat16(v[i]));
    *(uint4*)(g_Ah + (size_t)b * FF + 8 * t) = *(uint4*)h;
}

// features -> bf16 rows. grid=SS, block=256
__global__ void k_convB(const float* __restrict__ f) {
    int n = blockIdx.x, t = threadIdx.x;
    const float4* r = (const float4*)(f + (size_t)n * FF);
    float4 v0 = r[2 * t], v1 = r[2 * t + 1];
    float v[8] = { v0.x, v0.y, v0.z, v0.w, v1.x, v1.y, v1.z, v1.w };
    __align__(16) unsigned short h[8];
    #pragma unroll
    for (int i = 0; i < 8; i++) h[i] = __bfloat16_as_ushort(__float2bfloat16(v[i]));
    *(uint4*)(g_Bh + (size_t)n * FF + 8 * t) = *(uint4*)h;
}

// bulk copy features -> out (out only 4B-aligned). grid=2048, block=256
__global__ void k_copy(const float* __restrict__ f, float* __restrict__ out) {
    size_t n4 = (size_t)SS * FF / 4;
    for (size_t i = (size_t)blockIdx.x * blockDim.x + threadIdx.x; i < n4;
         i += (size_t)gridDim.x * blockDim.x) {
        float4 v = ((const float4*)f)[i];
        float* o = out + i * 4;
        o[0] = v.x; o[1] = v.y; o[2] = v.z; o[3] = v.w;
    }
}

// ---------------- big GEMM fused with NCE partial sums ----------------
#define STRIDE 40
#define A_TILE_B (128 * STRIDE * 2)
#define B_TILE_B (64 * STRIDE * 2)
#define STAGE_B  (A_TILE_B + B_TILE_B)
#define NCH 64
#define NSTG 6

__device__ __forceinline__ void gemm_issue(int c, int bm, int bn, int tid, uint32_t sb) {
    if (c < NCH) {
        uint32_t st = sb + (c % NSTG) * STAGE_B;
        #pragma unroll
        for (int i = 0; i < 2; i++) {
            int q = tid + i * 256;
            int row = q >> 2, qc = q & 3;
            cp16(st + row * (STRIDE * 2) + qc * 16,
                 (const char*)(g_Ah + (size_t)(bm + row) * FF + c * 32) + qc * 16);
        }
        {
            int row = tid >> 2, qc = tid & 3;
            cp16(st + A_TILE_B + row * (STRIDE * 2) + qc * 16,
                 (const char*)(g_Bh + (size_t)(bn + row) * FF + c * 32) + qc * 16);
        }
    }
    cp_commit();
}

__global__ void __launch_bounds__(256) k_gemm_mma() {
    extern __shared__ __align__(128) unsigned char smem[];
    uint32_t sb = smem_u32(smem);
    int tid = threadIdx.x;
    int bn = blockIdx.x * 64, bm = blockIdx.y * 128;
    int wid = tid >> 5, lane = tid & 31;
    int wm = (wid >> 1) * 32, wn = (wid & 1) * 32;
    int mi = lane >> 3, lr = lane & 7;
    uint32_t aoff = (uint32_t)(((wm + lr + (mi & 1) * 8) * STRIDE + (mi >> 1) * 8) * 2);
    uint32_t boff = (uint32_t)(A_TILE_B + ((wn + lr + (mi >> 1) * 8) * STRIDE + (mi & 1) * 8) * 2);

    float acc[2][4][4];
    #pragma unroll
    for (int i = 0; i < 2; i++)
        #pragma unroll
        for (int j = 0; j < 4; j++)
            #pragma unroll
            for (int q = 0; q < 4; q++) acc[i][j][q] = 0.f;

    #pragma unroll
    for (int p = 0; p < NSTG - 1; p++) gemm_issue(p, bm, bn, tid, sb);

    for (int c = 0; c < NCH; c++) {
        cp_wait4();
        __syncthreads();
        gemm_issue(c + NSTG - 1, bm, bn, tid, sb);
        uint32_t st = sb + (c % NSTG) * STAGE_B;
        uint32_t a[2][2][4], b[2][2][4];
        #pragma unroll
        for (int ks = 0; ks < 2; ks++) {
            ldsm4(a[ks][0], st + aoff + (0 * 16 * STRIDE + ks * 16) * 2);
            ldsm4(a[ks][1], st + aoff + (1 * 16 * STRIDE + ks * 16) * 2);
            ldsm4(b[ks][0], st + boff + (0 * 16 * STRIDE + ks * 16) * 2);
            ldsm4(b[ks][1], st + boff + (1 * 16 * STRIDE + ks * 16) * 2);
        }
        #pragma unroll
        for (int ks = 0; ks < 2; ks++)
            #pragma unroll
            for (int i = 0; i < 2; i++)
                #pragma unroll
                for (int j = 0; j < 4; j++)
                    mma_bf16(acc[i][j], a[ks][i],
                             b[ks][j >> 1][(j & 1) * 2], b[ks][j >> 1][(j & 1) * 2 + 1]);
    }

    // fused NCE epilogue: per-row sum of exp(20*acc - 20)
    #pragma unroll
    for (int i = 0; i < 2; i++) {
        float z0 = 0.f, z1 = 0.f;
        #pragma unroll
        for (int j = 0; j < 4; j++) {
            z0 += __expf(fmaf(acc[i][j][0], 20.f, -20.f)) + __expf(fmaf(acc[i][j][1], 20.f, -20.f));
            z1 += __expf(fmaf(acc[i][j][2], 20.f, -20.f)) + __expf(fmaf(acc[i][j][3], 20.f, -20.f));
        }
        z0 += __shfl_xor_sync(0xffffffffu, z0, 1);
        z0 += __shfl_xor_sync(0xffffffffu, z0, 2);
        z1 += __shfl_xor_sync(0xffffffffu, z1, 1);
        z1 += __shfl_xor_sync(0xffffffffu, z1, 2);
        if ((lane & 3) == 0) {
            int r0 = bm + wm + i * 16 + (lane >> 2);
            atomicAdd(&g_Zn[r0], z0);
            atomicAdd(&g_Zn[r0 + 8], z1);
        }
    }
}

// NCE finalize. grid=BB, block=256
__global__ void k_nce2(const int* __restrict__ targets, const float* __restrict__ feat) {
    int b = blockIdx.x, t = threadIdx.x;
    int tb = targets[b];
    const float4* xr = (const float4*)(g_x + (size_t)b * FF);
    const float4* fr = (const float4*)(feat + (size_t)tb * FF);
    float s = 0.f;
    #pragma unroll
    for (int i = 0; i < 2; i++) {
        float4 xv = xr[t + i * 256], fv = fr[t + i * 256];
        s += xv.x * fv.x + xv.y * fv.y + xv.z * fv.z + xv.w * fv.w;
    }
    s = bsum(s);
    if (t == 0) atomicAdd(&g_acc[0], (20.f + logf(g_Zn[b])) - 20.f * s);
}

// single-pass per-row max/sumexp + fp16 E, row cached in registers. grid=(BB,2), block=256
__global__ void __launch_bounds__(256) k_stats(const float* __restrict__ l0,
                                               const float* __restrict__ l1) {
    int b = blockIdx.x, which = blockIdx.y, t = threadIdx.x;
    if (b == 0 && which == 0 && t == 0) g_acc[2] = 0.f;   // zeroed before wbuild (stream order)
    const float4* row = (const float4*)((which ? l1 : l0) + (size_t)b * SS);
    float4 v[8];
    #pragma unroll
    for (int i = 0; i < 8; i++) v[i] = row[t + i * 256];
    float m = -1e30f;
    #pragma unroll
    for (int i = 0; i < 8; i++)
        m = fmaxf(m, fmaxf(fmaxf(v[i].x, v[i].y), fmaxf(v[i].z, v[i].w)));
    m = bmax(m);
    float z = 0.f;
    __half* er = g_Eh + (size_t)(which * BB + b) * SS;
    #pragma unroll
    for (int i = 0; i < 8; i++) {
        float e0 = expf(v[i].x - m), e1 = expf(v[i].y - m);
        float e2 = expf(v[i].z - m), e3 = expf(v[i].w - m);
        z += (e0 + e1) + (e2 + e3);
        __align__(8) __half h[4] = { __float2half(e0), __float2half(e1),
                                     __float2half(e2), __float2half(e3) };
        *(uint2*)(er + 4 * (t + i * 256)) = *(uint2*)h;
    }
    z = bsum(z);
    if (t == 0) {
        g_Z [which * BB + b] = z;
        g_lZ[which * BB + b] = m + logf(z);
    }
}

// build fp16 weight matrix W [512][512] (x1024) + CE target term. grid=BB, block=256
__global__ void k_wbuild(const int* __restrict__ neighbors, const float* __restrict__ ndist,
                         const int* __restrict__ targets, const float* __restrict__ l0) {
    int b = blockIdx.x, t = threadIdx.x;
    if (b == 0 && t == 0) { g_acc[1] = 0.f; g_acc[3] = 0.f; }  // before ngemm (stream order)
    __shared__ float rw[512], ru[256], ew[KNB];
    __shared__ int nk[KNB];
    __shared__ float ssum;
    rw[t] = 0.f; rw[t + 256] = 0.f; ru[t] = 0.f;
    if (t < KNB) {
        nk[t] = neighbors[b * KNB + t];
        ew[t] = expf(ndist[b * KNB + t] * (1.0f / 0.6f));
    }
    __syncthreads();
    if (t == 0) { float s = 0.f; for (int k = 0; k < KNB; k++) s += ew[k]; ssum = s; }
    __syncthreads();
    if (t < KNB) {
        float w = ew[t] / (2.0f * ssum);
        int n = nk[t];
        atomicAdd(&rw[n],       w / g_Z[n]);
        atomicAdd(&rw[256 + n], w / g_Z[BB + n]);
        atomicAdd(&ru[n], 1.0f / ((float)KNB * g_Z[n]));
    }
    __syncthreads();
    __half* W0 = g_Wh + (size_t)b * 512;
    __half* W1 = g_Wh + (size_t)(256 + b) * 512;
    W0[t]       = __float2half(rw[t] * 1024.f);
    W0[t + 256] = __float2half(rw[t + 256] * 1024.f);
    W1[t]       = __float2half(ru[t] * 1024.f);
    W1[t + 256] = __float2half(0.f);
    if (t == 0)
        atomicAdd(&g_acc[2], l0[(size_t)b * SS + targets[b]] - g_lZ[b]);  // lp0[target]
}

// ---------------- neighbor GEMM, fused CE/KL epilogue ----------------
#define NNCH 16
#define ESTR 144
#define EOFF A_TILE_B
#define STAGE2_B (A_TILE_B + 32 * ESTR)

__device__ __forceinline__ void ngemm_issue(int c, int bm, int bn, int tid, uint32_t sb) {
    if (c < NNCH) {
        uint32_t st = sb + (c & 3) * STAGE2_B;
        #pragma unroll
        for (int i = 0; i < 2; i++) {          // W tile: 128 rows x 64B
            int q = tid + i * 256;
            int row = q >> 2, qc = q & 3;
            cp16(st + row * (STRIDE * 2) + qc * 16,
                 (const char*)(g_Wh + (size_t)(bm + row) * 512 + c * 32) + qc * 16);
        }
        {                                       // E tile: 32 k-rows x 128B
            int row = tid >> 3, seg = tid & 7;
            cp16(st + EOFF + row * ESTR + seg * 16,
                 (const char*)(g_Eh + (size_t)(c * 32 + row) * SS + bn + seg * 8));
        }
    }
    cp_commit();
}

__global__ void __launch_bounds__(256) k_ngemm(const float* __restrict__ l0,
                                               const float* __restrict__ l1) {
    extern __shared__ __align__(128) unsigned char smem[];
    uint32_t sb = smem_u32(smem);
    int tid = threadIdx.x;
    int bn = blockIdx.x * 64, bm = blockIdx.y * 128;
    int wid = tid >> 5, lane = tid & 31;
    int wm = (wid >> 1) * 32, wn = (wid & 1) * 32;
    int mi = lane >> 3, lr = lane & 7;
    uint32_t aoff = (uint32_t)(((wm + lr + (mi & 1) * 8) * STRIDE + (mi >> 1) * 8) * 2);
    uint32_t ebase = (uint32_t)(EOFF + ((mi & 1) * 8 + lr) * ESTR + (wn + (mi >> 1) * 8) * 2);

    float acc[2][4][4];
    #pragma unroll
    for (int i = 0; i < 2; i++)
        #pragma unroll
        for (int j = 0; j < 4; j++)
            #pragma unroll
            for (int q = 0; q < 4; q++) acc[i][j][q] = 0.f;

    ngemm_issue(0, bm, bn, tid, sb);
    ngemm_issue(1, bm, bn, tid, sb);
    ngemm_issue(2, bm, bn, tid, sb);

    for (int c = 0; c < NNCH; c++) {
        cp_wait2();
        __syncthreads();
        ngemm_issue(c + 3, bm, bn, tid, sb);
        uint32_t st = sb + (c & 3) * STAGE2_B;
        uint32_t a[2][2][4], b[2][2][4];
        #pragma unroll
        for (int ks = 0; ks < 2; ks++) {
            ldsm4 (a[ks][0], st + aoff + (0 * 16 * STRIDE + ks * 16) * 2);
            ldsm4 (a[ks][1], st + aoff + (1 * 16 * STRIDE + ks * 16) * 2);
            ldsm4t(b[ks][0], st + ebase + ks * (16 * ESTR) + 0 * 32);
            ldsm4t(b[ks][1], st + ebase + ks * (16 * ESTR) + 1 * 32);
        }
        #pragma unroll
        for (int ks = 0; ks < 2; ks++)
            #pragma unroll
            for (int i = 0; i < 2; i++)
                #pragma unroll
                for (int j = 0; j < 4; j++)
                    mma_f16(acc[i][j], a[ks][i],
                            b[ks][j >> 1][(j & 1) * 2], b[ks][j >> 1][(j & 1) * 2 + 1]);
    }

    const float S = 1.0f / 1024.f;
    int isKL = (bm >= 256);
    const float* L = isKL ? l1 : l0;
    int roff = isKL ? 256 : 0;
    float part = 0.f;
    #pragma unroll
    for (int i = 0; i < 2; i++) {
        int r0 = bm + wm + i * 16 + (lane >> 2);
        float lz0 = g_lZ[r0], lz1 = g_lZ[r0 + 8];
        const float* row0 = L + (size_t)(r0 - roff) * SS;
        const float* row1 = row0 + 8 * (size_t)SS;
        #pragma unroll
        for (int j = 0; j < 4; j++) {
            int col = bn + wn + j * 8 + (lane & 3) * 2;
            float2 p0 = *(const float2*)(row0 + col);
            float2 p1 = *(const float2*)(row1 + col);
            float v0 = acc[i][j][0] * S, v1 = acc[i][j][1] * S;
            float v2 = acc[i][j][2] * S, v3 = acc[i][j][3] * S;
            if (isKL) {
                part += v0 * (__logf(fmaxf(v0, 1e-12f)) - (p0.x - lz0));
                part += v1 * (__logf(fmaxf(v1, 1e-12f)) - (p0.y - lz0));
                part += v2 * (__logf(fmaxf(v2, 1e-12f)) - (p1.x - lz1));
                part += v3 * (__logf(fmaxf(v3, 1e-12f)) - (p1.y - lz1));
            } else {
                part += v0 * (p0.x - lz0) + v1 * (p0.y - lz0);
                part += v2 * (p1.x - lz1) + v3 * (p1.y - lz1);
            }
        }
    }
    part = bsum(part);
    if (tid == 0) atomicAdd(&g_acc[isKL ? 3 : 1], part);
}

__global__ void k_fin(float* __restrict__ out, const float* __restrict__ ramp) {
    if (threadIdx.x == 0) {
        const float invB = 1.0f / 256.0f;
        out[0] = g_acc[0] * invB;                                   // loss_nce
        out[1] = -(0.9f * g_acc[2] + 0.1f * g_acc[1]) * invB;       // loss_ce
        out[2] = ramp[0] * g_acc[3] * invB;                         // kl
    }
}

// momentum update of targeted rows (last occurrence wins). grid=BB, block=256
__global__ void k_upd(const float* __restrict__ f, const int* __restrict__ targets,
                      float* __restrict__ out) {
    int b = blockIdx.x, t = threadIdx.x;
    __shared__ int flag;
    int tb = targets[b];
    if (t == 0) {
        int ok = 1;
        for (int j = b + 1; j < BB; j++)
            if (targets[j] == tb) { ok = 0; break; }
        flag = ok;
    }
    __syncthreads();
    if (!flag) return;
    const float* fr = f   + (size_t)tb * FF;
    const float* xr = g_x + (size_t)b  * FF;
    float u[8];
    float s = 0.f;
    #pragma unroll
    for (int i = 0; i < 8; i++) {
        float v = 0.2f * fr[t + i * 256] + 0.8f * xr[t + i * 256];
        u[i] = v; s += v * v;
    }
    s = bsum(s);
    float inv = 1.f / fmaxf(sqrtf(s), 1e-12f);
    float* orow = out + (size_t)tb * FF;
    #pragma unroll
    for (int i = 0; i < 8; i++) orow[t + i * 256] = u[i] * inv;
}

extern "C" void kernel_launch(void* const* d_in, const int* in_sizes, int n_in,
                              void* d_out, int out_size) {
    const float* inputs0   = (const float*)d_in[0];
    const float* l0        = (const float*)d_in[1];
    const float* l1        = (const float*)d_in[2];
    const int*   targets   = (const int*)d_in[3];
    const int*   neighbors = (const int*)d_in[5];
    const float* ndist     = (const float*)d_in[6];
    const float* ramp      = (const float*)d_in[7];
    const float* feat      = (const float*)d_in[8];
    float* out = (float*)d_out;

    static cudaStream_t s1 = 0, s2 = 0;
    static cudaEvent_t e_start = 0, e_norm = 0, e_c1 = 0, e_c2 = 0;
    static int inited = 0;
    if (!inited) {
        cudaFuncSetAttribute(k_gemm_mma, cudaFuncAttributeMaxDynamicSharedMemorySize,
                             NSTG * STAGE_B);
        cudaFuncSetAttribute(k_ngemm, cudaFuncAttributeMaxDynamicSharedMemorySize,
                             4 * STAGE2_B);
        cudaStreamCreateWithFlags(&s1, cudaStreamNonBlocking);
        cudaStreamCreateWithFlags(&s2, cudaStreamNonBlocking);
        cudaEventCreateWithFlags(&e_start, cudaEventDisableTiming);
        cudaEventCreateWithFlags(&e_norm, cudaEventDisableTiming);
        cudaEventCreateWithFlags(&e_c1, cudaEventDisableTiming);
        cudaEventCreateWithFlags(&e_c2, cudaEventDisableTiming);
        inited = 1;
    }

    // fork point at the very start (pulls s1/s2 into the capture immediately)
    cudaEventRecord(e_start, 0);

    // ---- chain3 (s1): feature copy (independent) -> momentum update (needs g_x) ----
    cudaStreamWaitEvent(s1, e_start, 0);
    k_copy<<<2048, 256, 0, s1>>>(feat, out + 3);

    // ---- chain2 (s2): softmax stats -> W build -> neighbor GEMM (independent of norm) ----
    cudaStreamWaitEvent(s2, e_start, 0);
    dim3 gs(BB, 2);
    k_stats<<<gs, 256, 0, s2>>>(l0, l1);
    k_wbuild<<<BB, 256, 0, s2>>>(neighbors, ndist, targets, l0);
    dim3 gn(SS / 64, 4);
    k_ngemm<<<gn, 256, 4 * STAGE2_B, s2>>>(l0, l1);
    cudaEventRecord(e_c2, s2);

    // ---- chain1 (main): norm -> convB -> big GEMM -> NCE ----
    k_norm<<<BB, 256>>>(inputs0);
    cudaEventRecord(e_norm, 0);
    cudaStreamWaitEvent(s1, e_norm, 0);
    k_upd<<<BB, 256, 0, s1>>>(feat, targets, out + 3);
    cudaEventRecord(e_c1, s1);

    k_convB<<<SS, 256>>>(feat);
    dim3 gg(SS / 64, BB / 128);
    k_gemm_mma<<<gg, 256, NSTG * STAGE_B>>>();
    k_nce2<<<BB, 256>>>(targets, feat);

    // join and finalize
    cudaStreamWaitEvent(0, e_c1, 0);
    cudaStreamWaitEvent(0, e_c2, 0);
    k_fin<<<1, 32>>>(out, ramp);
}